// round 13
// baseline (speedup 1.0000x reference)
#include <cuda_runtime.h>
#include <cstddef>

#define BATCH 8
#define LFRM  64
#define CH    3
#define HH    224
#define WW    224
#define HWSZ  (HH*WW)            // 50176
#define FRAMES (BATCH*LFRM)      // 512
#define PAIRS  (BATCH*(LFRM-1))  // 504
#define MSEL   16
#define EPSF   1e-6f

#define G      3                 // pairs per block (63 = 21*3)
#define NGRP   (BATCH*21)        // 168 pair-groups
#define NCHUNK 4                 // row chunks per pair
#define CROWS  56                // output rows per chunk (4*56 = 224)
#define INROWS 62                // input rows: 56 + 6 halo
#define NWARP  9                 // column strips of 26 outputs (9*26 = 234 >= 224)
#define NTHR   (NWARP*32)        // 288

// ---------------- scratch (static device globals; no allocation) -------------
__device__ double g_ds4[PAIRS * NCHUNK];        // per-(pair,chunk) partial diff scores
__device__ int    g_idx[BATCH * MSEL];          // selected frame indices

// ============================================================================
// kernel 1: fused channel-sum + 7x7 box + pairwise |w0*box + eps| reduction
//
// Barrier-free mainloop. Warp = 26-output column strip (32 loaded cols, 6 halo
// lanes). Horizontal 7-tap via warp shuffles; vertical 7-tap via per-lane
// register ring. Each warp streams 62 rows with no syncs -> LDG latency hidden
// by in-warp MLP. G=3 pairs per block (4 frames, 12 coalesced loads/lane/row).
// ============================================================================
__global__ __launch_bounds__(NTHR) void pairdiff_kernel(const float* __restrict__ x,
                                                        const float* __restrict__ wgt)
{
    const int t     = threadIdx.x;
    const int warp  = t >> 5;
    const int lane  = t & 31;
    const int chunk = blockIdx.x;                    // 0..3
    const int grp   = blockIdx.y;                    // 0..167
    const int b     = grp / 21;
    const int l0    = (grp % 21) * G;
    const int r0    = chunk * CROWS;

    const float w0 = __ldg(wgt);                     // uniform conv weight
    const float* xf = x + (size_t)(b * LFRM + l0) * (CH * HWSZ);  // frames l0..l0+3

    const int  cload    = warp * 26 + lane - 3;      // loaded column
    const bool loadcol  = (cload >= 0) && (cload < WW);
    const bool outcol   = (lane >= 3) && (lane <= 28) && (cload < WW);
    const float* colp   = xf + (loadcol ? cload : 0);

    float hb[G][8];                                  // vertical register rings
#pragma unroll
    for (int p = 0; p < G; p++)
#pragma unroll
        for (int k = 0; k < 8; k++) hb[p][k] = 0.f;
    double acc[G][2];
#pragma unroll
    for (int p = 0; p < G; p++) { acc[p][0] = 0.0; acc[p][1] = 0.0; }

#pragma unroll 1
    for (int jo = 0; jo < 64; jo += 8) {
#pragma unroll
        for (int e = 0; e < 8; e++) {
            const int j = jo + e;                    // j % 8 == e (static ring slot)
            if (j >= INROWS) continue;               // block-uniform predicate
            const int i = r0 - 3 + j;
            const bool ok = ((unsigned)i < (unsigned)HH) && loadcol;
            const float* rp = colp + (ptrdiff_t)i * WW;

            float lv[12];
#pragma unroll
            for (int q = 0; q < 12; q++)
                lv[q] = ok ? __ldg(rp + (size_t)q * HWSZ) : 0.f;

            const float s0 = (lv[0] + lv[1])  + lv[2];
            const float s1 = (lv[3] + lv[4])  + lv[5];
            const float s2 = (lv[6] + lv[7])  + lv[8];
            const float s3 = (lv[9] + lv[10]) + lv[11];
            const float d0 = s0 - s1, d1 = s1 - s2, d2 = s2 - s3;
            const float dv[G] = {d0, d1, d2};

            // horizontal 7-tap via shuffles (tree matches smem version:
            // ((c-3 + c-2) + (c-1 + c0)) + ((c+1 + c+2) + c+3))
#pragma unroll
            for (int p = 0; p < G; p++) {
                const float dp = dv[p];
                const float u1 = __shfl_up_sync(0xffffffffu, dp, 1);
                const float u2 = __shfl_up_sync(0xffffffffu, dp, 2);
                const float u3 = __shfl_up_sync(0xffffffffu, dp, 3);
                const float w1 = __shfl_down_sync(0xffffffffu, dp, 1);
                const float w2 = __shfl_down_sync(0xffffffffu, dp, 2);
                const float w3 = __shfl_down_sync(0xffffffffu, dp, 3);
                hb[p][e] = ((u3 + u2) + (u1 + dp)) + ((w1 + w2) + w3);
            }

            if (j >= 6 && j < 6 + CROWS) {           // output row r0 + j - 6
#pragma unroll
                for (int p = 0; p < G; p++) {
                    const float vs =
                        ((hb[p][(e)     & 7] + hb[p][(e + 7) & 7])
                      +  (hb[p][(e + 6) & 7] + hb[p][(e + 5) & 7]))
                      + ((hb[p][(e + 4) & 7] + hb[p][(e + 3) & 7])
                      +   hb[p][(e + 2) & 7]);
                    if (outcol)
                        acc[p][e & 1] += (double)fabsf(fmaf(w0, vs, EPSF));
                }
            }
        }
    }

    // ---- block reduction of double partials, per pair ----
    __shared__ double sd[NTHR];
#pragma unroll 1
    for (int p = 0; p < G; p++) {
        __syncthreads();
        sd[t] = acc[p][0] + acc[p][1];
        __syncthreads();
        if (t < 144) sd[t] += sd[t + 144];
        __syncthreads();
        if (t < 72)  sd[t] += sd[t + 72];
        __syncthreads();
        if (t < 36)  sd[t] += sd[t + 36];
        __syncthreads();
        if (t < 18)  sd[t] += sd[t + 18];
        __syncthreads();
        if (t < 9)   sd[t] += sd[t + 9];
        __syncthreads();
        if (t == 0) {
            double s = sd[0];
            for (int q = 1; q < 9; q++) s += sd[q];
            g_ds4[(b * (LFRM - 1) + l0 + p) * NCHUNK + chunk] = s;
        }
    }
}

// ---------------- kernel 2: sqrt / normalize / cumsum / argmin (parallel) ----
__global__ __launch_bounds__(512) void select_kernel()
{
    __shared__ double dsp[PAIRS];
    __shared__ double cum[PAIRS];
    const int t = threadIdx.x;

    if (t < PAIRS) {
        const double* q = &g_ds4[t * NCHUNK];
        dsp[t] = sqrt((q[0] + q[1]) + (q[2] + q[3]));
    }
    __syncthreads();

    if (t < BATCH) {
        const double* dp = &dsp[t * (LFRM - 1)];
        double s = 0.0;
        for (int l = 0; l < LFRM - 1; l++) s += dp[l];
        const double inv = 1.0 / s;
        double c = 0.0;
        for (int l = 0; l < LFRM - 1; l++) {
            c += dp[l] * inv;
            cum[t * (LFRM - 1) + l] = c;
        }
    }
    __syncthreads();

    if (t < BATCH * MSEL) {
        const int b = t >> 4, m = t & 15;
        const double* cp = &cum[b * (LFRM - 1)];
        const float interval = 1.0f / (float)(MSEL - 1);
        const double target = (double)((float)m * interval);
        double best = 1e300;
        int bi = 0;
        for (int l = 0; l < LFRM - 1; l++) {
            double d = fabs(cp[l] - target);
            if (d < best) { best = d; bi = l; }   // strict '<' => first occurrence
        }
        g_idx[t] = bi;
    }
}

// ---------------- kernel 3: gather selected frames ---------------------------
__global__ __launch_bounds__(256) void gather_kernel(const float* __restrict__ x,
                                                     float* __restrict__ out)
{
    const int bm = blockIdx.y;             // 0..127
    const int b  = bm >> 4;
    const int src = b * LFRM + g_idx[bm];
    const float4* sp = (const float4*)(x + (size_t)src * (CH * HWSZ));
    float4* dp = (float4*)(out + (size_t)bm * (CH * HWSZ));
    const int i = blockIdx.x * 256 + threadIdx.x;   // 147*256 = 37632 exact
    dp[i] = sp[i];
}

// ---------------- launcher ---------------------------------------------------
extern "C" void kernel_launch(void* const* d_in, const int* in_sizes, int n_in,
                              void* d_out, int out_size)
{
    const float* x = nullptr;
    const float* w = nullptr;
    for (int i = 0; i < n_in; i++) {
        if (in_sizes[i] == FRAMES * CH * HWSZ) x = (const float*)d_in[i];
        else if (in_sizes[i] == CH * 49)       w = (const float*)d_in[i];
    }

    pairdiff_kernel<<<dim3(NCHUNK, NGRP), NTHR>>>(x, w);
    select_kernel<<<1, 512>>>();
    gather_kernel<<<dim3(147, BATCH * MSEL), 256>>>(x, (float*)d_out);
}

// round 14
// speedup vs baseline: 1.0179x; 1.0179x over previous
#include <cuda_runtime.h>
#include <cstddef>

#define BATCH 8
#define LFRM  64
#define CH    3
#define HH    224
#define WW    224
#define HWSZ  (HH*WW)            // 50176
#define FRAMES (BATCH*LFRM)      // 512
#define PAIRS  (BATCH*(LFRM-1))  // 504
#define MSEL   16
#define EPSF   1e-6f

#define NCHUNK 4                 // row chunks per pair
#define CROWS  56                // output rows per chunk (4*56 = 224)
#define INROWS 62                // input rows: 56 + 6 halo
#define PPB    2                 // pairs per block
#define NGRP   (PAIRS/PPB)       // 252 blocks in y

// ---------------- scratch (static device globals; no allocation) -------------
__device__ double g_ds4[PAIRS * NCHUNK];        // per-(pair,chunk) partial diff scores
__device__ int    g_idx[BATCH * MSEL];          // selected frame indices

__device__ __forceinline__ float4 f4add(float4 a, float4 b) {
    return make_float4(a.x + b.x, a.y + b.y, a.z + b.z, a.w + b.w);
}
__device__ __forceinline__ float4 f4sub(float4 a, float4 b) {
    return make_float4(a.x - b.x, a.y - b.y, a.z - b.z, a.w - b.w);
}

// ============================================================================
// kernel 1: fused channel-sum + 7x7 box + pairwise |w0*box + eps| reduction
//
// Barrier-free vectorized mainloop. Warp = (pair, column-half); lane owns a
// float4 (4 cols). Per input row: 6x LDG.128 (2 frames x 3 ch) -> channel sums
// -> diff float4 -> horizontal 7-tap via own float4 + 6 scalar shuffles ->
// vertical 7-tap in float4 register ring -> |w0*vs+eps| into 4 double chains.
// No __syncthreads in the stream; LDG latency hidden by in-warp MLP.
// ============================================================================
__global__ __launch_bounds__(128, 6) void pairdiff_kernel(const float* __restrict__ x,
                                                          const float* __restrict__ wgt)
{
    const int t     = threadIdx.x;
    const int warp  = t >> 5;                         // 0..3
    const int lane  = t & 31;
    const int pofs  = warp >> 1;                      // pair offset in block
    const int half  = warp & 1;                       // column half
    const int chunk = blockIdx.x;                     // 0..3
    const int p     = blockIdx.y * PPB + pofs;        // 0..503
    const int b     = p / (LFRM - 1);
    const int l     = p - b * (LFRM - 1);
    const int r0    = chunk * CROWS;

    const float w0 = __ldg(wgt);                      // uniform conv weight
    const float* xl = x + (size_t)(b * LFRM + l) * (CH * HWSZ);  // frames l, l+1

    // lane L owns output cols obase..obase+3 (lanes 1..28); loads float4 at obase
    const int  obase = 4 * (lane - 1) + 112 * half;
    const bool ldok  = (obase >= 0) && (obase < WW) && (lane <= 29);
    const bool outok = (lane >= 1) && (lane <= 28);
    const float* colp = xl + (ldok ? obase : 0);

    float4 hb[8];                                     // vertical ring (float4)
#pragma unroll
    for (int k = 0; k < 8; k++) hb[k] = make_float4(0.f, 0.f, 0.f, 0.f);
    double acc[4] = {0.0, 0.0, 0.0, 0.0};             // one chain per component

#pragma unroll 1
    for (int jo = 0; jo < 64; jo += 8) {
#pragma unroll
        for (int e = 0; e < 8; e++) {
            const int j = jo + e;                     // ring slot == e (static)
            if (j >= INROWS) continue;                // uniform predicate
            const int i = r0 - 3 + j;
            const bool ok = ldok && ((unsigned)i < (unsigned)HH);
            const float* rp = colp + (ptrdiff_t)i * WW;

            const float4 z = make_float4(0.f, 0.f, 0.f, 0.f);
            float4 v0 = ok ? __ldg((const float4*)(rp))                    : z;
            float4 v1 = ok ? __ldg((const float4*)(rp + (size_t)1 * HWSZ)) : z;
            float4 v2 = ok ? __ldg((const float4*)(rp + (size_t)2 * HWSZ)) : z;
            float4 v3 = ok ? __ldg((const float4*)(rp + (size_t)3 * HWSZ)) : z;
            float4 v4 = ok ? __ldg((const float4*)(rp + (size_t)4 * HWSZ)) : z;
            float4 v5 = ok ? __ldg((const float4*)(rp + (size_t)5 * HWSZ)) : z;

            const float4 s0 = f4add(f4add(v0, v1), v2);   // frame l channel sum
            const float4 s1 = f4add(f4add(v3, v4), v5);   // frame l+1 channel sum
            const float4 d  = f4sub(s0, s1);

            // neighbor halo: left lane's y,z,w ; right lane's x,y,z
            const float Ly = __shfl_up_sync(0xffffffffu, d.y, 1);
            const float Lz = __shfl_up_sync(0xffffffffu, d.z, 1);
            const float Lw = __shfl_up_sync(0xffffffffu, d.w, 1);
            const float Rx = __shfl_down_sync(0xffffffffu, d.x, 1);
            const float Ry = __shfl_down_sync(0xffffffffu, d.y, 1);
            const float Rz = __shfl_down_sync(0xffffffffu, d.z, 1);

            // horizontal 7-tap box for the 4 owned columns
            float4 h;
            h.x = ((Ly + Lz) + (Lw + d.x)) + ((d.y + d.z) + d.w);
            h.y = ((Lz + Lw) + (d.x + d.y)) + ((d.z + d.w) + Rx);
            h.z = ((Lw + d.x) + (d.y + d.z)) + ((d.w + Rx) + Ry);
            h.w = ((d.x + d.y) + (d.z + d.w)) + ((Rx + Ry) + Rz);
            hb[e] = h;

            if (j >= 6) {                             // output row r0 + j - 6
                const float4 vs =
                    f4add(f4add(f4add(hb[(e)     & 7], hb[(e + 7) & 7]),
                                f4add(hb[(e + 6) & 7], hb[(e + 5) & 7])),
                          f4add(f4add(hb[(e + 4) & 7], hb[(e + 3) & 7]),
                                hb[(e + 2) & 7]));
                if (outok) {
                    acc[0] += (double)fabsf(fmaf(w0, vs.x, EPSF));
                    acc[1] += (double)fabsf(fmaf(w0, vs.y, EPSF));
                    acc[2] += (double)fabsf(fmaf(w0, vs.z, EPSF));
                    acc[3] += (double)fabsf(fmaf(w0, vs.w, EPSF));
                }
            }
        }
    }

    // ---- warp reduction (double), then cross-half combine ----
    double s = (acc[0] + acc[1]) + (acc[2] + acc[3]);
#pragma unroll
    for (int off = 16; off > 0; off >>= 1)
        s += __shfl_down_sync(0xffffffffu, s, off);

    __shared__ double sd[4];
    if (lane == 0) sd[warp] = s;
    __syncthreads();
    if (t < PPB) {
        const int pp = blockIdx.y * PPB + t;
        g_ds4[pp * NCHUNK + chunk] = sd[2 * t] + sd[2 * t + 1];
    }
}

// ---------------- kernel 2: sqrt / normalize / cumsum / argmin (parallel) ----
__global__ __launch_bounds__(512) void select_kernel()
{
    __shared__ double dsp[PAIRS];
    __shared__ double cum[PAIRS];
    const int t = threadIdx.x;

    if (t < PAIRS) {
        const double* q = &g_ds4[t * NCHUNK];
        dsp[t] = sqrt((q[0] + q[1]) + (q[2] + q[3]));
    }
    __syncthreads();

    if (t < BATCH) {
        const double* dp = &dsp[t * (LFRM - 1)];
        double s = 0.0;
        for (int l = 0; l < LFRM - 1; l++) s += dp[l];
        const double inv = 1.0 / s;
        double c = 0.0;
        for (int l = 0; l < LFRM - 1; l++) {
            c += dp[l] * inv;
            cum[t * (LFRM - 1) + l] = c;
        }
    }
    __syncthreads();

    if (t < BATCH * MSEL) {
        const int b = t >> 4, m = t & 15;
        const double* cp = &cum[b * (LFRM - 1)];
        const float interval = 1.0f / (float)(MSEL - 1);
        const double target = (double)((float)m * interval);
        double best = 1e300;
        int bi = 0;
        for (int l = 0; l < LFRM - 1; l++) {
            double d = fabs(cp[l] - target);
            if (d < best) { best = d; bi = l; }   // strict '<' => first occurrence
        }
        g_idx[t] = bi;
    }
}

// ---------------- kernel 3: gather selected frames ---------------------------
__global__ __launch_bounds__(256) void gather_kernel(const float* __restrict__ x,
                                                     float* __restrict__ out)
{
    const int bm = blockIdx.y;             // 0..127
    const int b  = bm >> 4;
    const int src = b * LFRM + g_idx[bm];
    const float4* sp = (const float4*)(x + (size_t)src * (CH * HWSZ));
    float4* dp = (float4*)(out + (size_t)bm * (CH * HWSZ));
    const int i = blockIdx.x * 256 + threadIdx.x;   // 147*256 = 37632 exact
    dp[i] = sp[i];
}

// ---------------- launcher ---------------------------------------------------
extern "C" void kernel_launch(void* const* d_in, const int* in_sizes, int n_in,
                              void* d_out, int out_size)
{
    const float* x = nullptr;
    const float* w = nullptr;
    for (int i = 0; i < n_in; i++) {
        if (in_sizes[i] == FRAMES * CH * HWSZ) x = (const float*)d_in[i];
        else if (in_sizes[i] == CH * 49)       w = (const float*)d_in[i];
    }

    pairdiff_kernel<<<dim3(NCHUNK, NGRP), 128>>>(x, w);
    select_kernel<<<1, 512>>>();
    gather_kernel<<<dim3(147, BATCH * MSEL), 256>>>(x, (float*)d_out);
}

// round 15
// speedup vs baseline: 1.0200x; 1.0021x over previous
#include <cuda_runtime.h>
#include <cstddef>

#define BATCH 8
#define LFRM  64
#define CH    3
#define HH    224
#define WW    224
#define HWSZ  (HH*WW)            // 50176
#define FRAMES (BATCH*LFRM)      // 512
#define PAIRS  (BATCH*(LFRM-1))  // 504
#define MSEL   16
#define EPSF   1e-6f

#define NCHUNK 4                 // row chunks per pair
#define CROWS  56                // output rows per chunk (4*56 = 224)
#define INROWS 62                // input rows: 56 + 6 halo
#define PPB    2                 // pairs per block
#define NGRP   (PAIRS/PPB)       // 252 blocks in y

// ---------------- scratch (static device globals; no allocation) -------------
__device__ double g_ds4[PAIRS * NCHUNK];        // per-(pair,chunk) partial diff scores
__device__ int    g_idx[BATCH * MSEL];          // selected frame indices

__device__ __forceinline__ float4 f4add(float4 a, float4 b) {
    return make_float4(a.x + b.x, a.y + b.y, a.z + b.z, a.w + b.w);
}
__device__ __forceinline__ float4 f4sub(float4 a, float4 b) {
    return make_float4(a.x - b.x, a.y - b.y, a.z - b.z, a.w - b.w);
}

// ============================================================================
// kernel 1: fused channel-sum + 7x7 box + pairwise |w0*box + eps| reduction
//
// Barrier-free vectorized mainloop. Warp = (pair, column-half); lane owns a
// float4 (4 cols). Per input row: 6x LDG.128 (2 frames x 3 ch) -> channel sums
// -> diff float4 -> horizontal 7-tap via own float4 + 6 scalar shuffles ->
// vertical 7-tap in float4 register ring -> |w0*vs+eps| into 4 double chains.
// No __syncthreads in the stream; LDG latency hidden by in-warp MLP.
// ============================================================================
__global__ __launch_bounds__(128, 6) void pairdiff_kernel(const float* __restrict__ x,
                                                          const float* __restrict__ wgt)
{
    const int t     = threadIdx.x;
    const int warp  = t >> 5;                         // 0..3
    const int lane  = t & 31;
    const int pofs  = warp >> 1;                      // pair offset in block
    const int half  = warp & 1;                       // column half
    const int chunk = blockIdx.x;                     // 0..3
    const int p     = blockIdx.y * PPB + pofs;        // 0..503
    const int b     = p / (LFRM - 1);
    const int l     = p - b * (LFRM - 1);
    const int r0    = chunk * CROWS;

    const float w0 = __ldg(wgt);                      // uniform conv weight
    const float* xl = x + (size_t)(b * LFRM + l) * (CH * HWSZ);  // frames l, l+1

    // lane L owns output cols obase..obase+3 (lanes 1..28); loads float4 at obase
    const int  obase = 4 * (lane - 1) + 112 * half;
    const bool ldok  = (obase >= 0) && (obase < WW) && (lane <= 29);
    const bool outok = (lane >= 1) && (lane <= 28);
    const float* colp = xl + (ldok ? obase : 0);

    float4 hb[8];                                     // vertical ring (float4)
#pragma unroll
    for (int k = 0; k < 8; k++) hb[k] = make_float4(0.f, 0.f, 0.f, 0.f);
    double acc[4] = {0.0, 0.0, 0.0, 0.0};             // one chain per component

#pragma unroll 1
    for (int jo = 0; jo < 64; jo += 8) {
#pragma unroll
        for (int e = 0; e < 8; e++) {
            const int j = jo + e;                     // ring slot == e (static)
            if (j >= INROWS) continue;                // uniform predicate
            const int i = r0 - 3 + j;
            const bool ok = ldok && ((unsigned)i < (unsigned)HH);
            const float* rp = colp + (ptrdiff_t)i * WW;

            const float4 z = make_float4(0.f, 0.f, 0.f, 0.f);
            float4 v0 = ok ? __ldg((const float4*)(rp))                    : z;
            float4 v1 = ok ? __ldg((const float4*)(rp + (size_t)1 * HWSZ)) : z;
            float4 v2 = ok ? __ldg((const float4*)(rp + (size_t)2 * HWSZ)) : z;
            float4 v3 = ok ? __ldg((const float4*)(rp + (size_t)3 * HWSZ)) : z;
            float4 v4 = ok ? __ldg((const float4*)(rp + (size_t)4 * HWSZ)) : z;
            float4 v5 = ok ? __ldg((const float4*)(rp + (size_t)5 * HWSZ)) : z;

            const float4 s0 = f4add(f4add(v0, v1), v2);   // frame l channel sum
            const float4 s1 = f4add(f4add(v3, v4), v5);   // frame l+1 channel sum
            const float4 d  = f4sub(s0, s1);

            // neighbor halo: left lane's y,z,w ; right lane's x,y,z
            const float Ly = __shfl_up_sync(0xffffffffu, d.y, 1);
            const float Lz = __shfl_up_sync(0xffffffffu, d.z, 1);
            const float Lw = __shfl_up_sync(0xffffffffu, d.w, 1);
            const float Rx = __shfl_down_sync(0xffffffffu, d.x, 1);
            const float Ry = __shfl_down_sync(0xffffffffu, d.y, 1);
            const float Rz = __shfl_down_sync(0xffffffffu, d.z, 1);

            // horizontal 7-tap box for the 4 owned columns
            float4 h;
            h.x = ((Ly + Lz) + (Lw + d.x)) + ((d.y + d.z) + d.w);
            h.y = ((Lz + Lw) + (d.x + d.y)) + ((d.z + d.w) + Rx);
            h.z = ((Lw + d.x) + (d.y + d.z)) + ((d.w + Rx) + Ry);
            h.w = ((d.x + d.y) + (d.z + d.w)) + ((Rx + Ry) + Rz);
            hb[e] = h;

            if (j >= 6) {                             // output row r0 + j - 6
                const float4 vs =
                    f4add(f4add(f4add(hb[(e)     & 7], hb[(e + 7) & 7]),
                                f4add(hb[(e + 6) & 7], hb[(e + 5) & 7])),
                          f4add(f4add(hb[(e + 4) & 7], hb[(e + 3) & 7]),
                                hb[(e + 2) & 7]));
                if (outok) {
                    acc[0] += (double)fabsf(fmaf(w0, vs.x, EPSF));
                    acc[1] += (double)fabsf(fmaf(w0, vs.y, EPSF));
                    acc[2] += (double)fabsf(fmaf(w0, vs.z, EPSF));
                    acc[3] += (double)fabsf(fmaf(w0, vs.w, EPSF));
                }
            }
        }
    }

    // ---- warp reduction (double), then cross-half combine ----
    double s = (acc[0] + acc[1]) + (acc[2] + acc[3]);
#pragma unroll
    for (int off = 16; off > 0; off >>= 1)
        s += __shfl_down_sync(0xffffffffu, s, off);

    __shared__ double sd[4];
    if (lane == 0) sd[warp] = s;
    __syncthreads();
    if (t < PPB) {
        const int pp = blockIdx.y * PPB + t;
        g_ds4[pp * NCHUNK + chunk] = sd[2 * t] + sd[2 * t + 1];
    }
}

// ---------------- kernel 2: sqrt / normalize / cumsum / argmin (parallel) ----
__global__ __launch_bounds__(512) void select_kernel()
{
    __shared__ double dsp[PAIRS];
    __shared__ double cum[PAIRS];
    const int t = threadIdx.x;

    if (t < PAIRS) {
        const double* q = &g_ds4[t * NCHUNK];
        dsp[t] = sqrt((q[0] + q[1]) + (q[2] + q[3]));
    }
    __syncthreads();

    if (t < BATCH) {
        const double* dp = &dsp[t * (LFRM - 1)];
        double s = 0.0;
        for (int l = 0; l < LFRM - 1; l++) s += dp[l];
        const double inv = 1.0 / s;
        double c = 0.0;
        for (int l = 0; l < LFRM - 1; l++) {
            c += dp[l] * inv;
            cum[t * (LFRM - 1) + l] = c;
        }
    }
    __syncthreads();

    if (t < BATCH * MSEL) {
        const int b = t >> 4, m = t & 15;
        const double* cp = &cum[b * (LFRM - 1)];
        const float interval = 1.0f / (float)(MSEL - 1);
        const double target = (double)((float)m * interval);
        double best = 1e300;
        int bi = 0;
        for (int l = 0; l < LFRM - 1; l++) {
            double d = fabs(cp[l] - target);
            if (d < best) { best = d; bi = l; }   // strict '<' => first occurrence
        }
        g_idx[t] = bi;
    }
}

// ---------------- kernel 3: gather selected frames ---------------------------
__global__ __launch_bounds__(256) void gather_kernel(const float* __restrict__ x,
                                                     float* __restrict__ out)
{
    const int bm = blockIdx.y;             // 0..127
    const int b  = bm >> 4;
    const int src = b * LFRM + g_idx[bm];
    const float4* sp = (const float4*)(x + (size_t)src * (CH * HWSZ));
    float4* dp = (float4*)(out + (size_t)bm * (CH * HWSZ));
    const int i = blockIdx.x * 256 + threadIdx.x;   // 147*256 = 37632 exact
    dp[i] = sp[i];
}

// ---------------- launcher ---------------------------------------------------
extern "C" void kernel_launch(void* const* d_in, const int* in_sizes, int n_in,
                              void* d_out, int out_size)
{
    const float* x = nullptr;
    const float* w = nullptr;
    for (int i = 0; i < n_in; i++) {
        if (in_sizes[i] == FRAMES * CH * HWSZ) x = (const float*)d_in[i];
        else if (in_sizes[i] == CH * 49)       w = (const float*)d_in[i];
    }

    pairdiff_kernel<<<dim3(NCHUNK, NGRP), 128>>>(x, w);
    select_kernel<<<1, 512>>>();
    gather_kernel<<<dim3(147, BATCH * MSEL), 256>>>(x, (float*)d_out);
}

// round 16
// speedup vs baseline: 1.0205x; 1.0004x over previous
#include <cuda_runtime.h>
#include <cstddef>

#define BATCH 8
#define LFRM  64
#define CH    3
#define HH    224
#define WW    224
#define HWSZ  (HH*WW)            // 50176
#define FRAMES (BATCH*LFRM)      // 512
#define PAIRS  (BATCH*(LFRM-1))  // 504
#define MSEL   16
#define EPSF   1e-6f

#define NCHUNK 4                 // row chunks per pair
#define CROWS  56                // output rows per chunk (4*56 = 224)
#define INROWS 62                // input rows: 56 + 6 halo
#define PPB    2                 // pairs per block
#define NGRP   (PAIRS/PPB)       // 252 blocks in y

// ---------------- scratch (static device globals; no allocation) -------------
__device__ double g_ds4[PAIRS * NCHUNK];        // per-(pair,chunk) partial diff scores
__device__ int    g_idx[BATCH * MSEL];          // selected frame indices

__device__ __forceinline__ float4 f4add(float4 a, float4 b) {
    return make_float4(a.x + b.x, a.y + b.y, a.z + b.z, a.w + b.w);
}
__device__ __forceinline__ float4 f4sub(float4 a, float4 b) {
    return make_float4(a.x - b.x, a.y - b.y, a.z - b.z, a.w - b.w);
}

// ============================================================================
// kernel 1: fused channel-sum + 7x7 box + pairwise |w0*box + eps| reduction
//
// Barrier-free vectorized mainloop. Warp = (pair, column-half); lane owns a
// float4 (4 cols). Per input row: 6x LDG.128 (2 frames x 3 ch) -> channel sums
// -> diff float4 -> horizontal 7-tap via own float4 + 6 scalar shuffles ->
// vertical 7-tap in float4 register ring -> |w0*vs+eps| into 4 double chains.
// No __syncthreads in the stream; LDG latency hidden by in-warp MLP.
// ============================================================================
__global__ __launch_bounds__(128, 6) void pairdiff_kernel(const float* __restrict__ x,
                                                          const float* __restrict__ wgt)
{
    const int t     = threadIdx.x;
    const int warp  = t >> 5;                         // 0..3
    const int lane  = t & 31;
    const int pofs  = warp >> 1;                      // pair offset in block
    const int half  = warp & 1;                       // column half
    const int chunk = blockIdx.x;                     // 0..3
    const int p     = blockIdx.y * PPB + pofs;        // 0..503
    const int b     = p / (LFRM - 1);
    const int l     = p - b * (LFRM - 1);
    const int r0    = chunk * CROWS;

    const float w0 = __ldg(wgt);                      // uniform conv weight
    const float* xl = x + (size_t)(b * LFRM + l) * (CH * HWSZ);  // frames l, l+1

    // lane L owns output cols obase..obase+3 (lanes 1..28); loads float4 at obase
    const int  obase = 4 * (lane - 1) + 112 * half;
    const bool ldok  = (obase >= 0) && (obase < WW) && (lane <= 29);
    const bool outok = (lane >= 1) && (lane <= 28);
    const float* colp = xl + (ldok ? obase : 0);

    float4 hb[8];                                     // vertical ring (float4)
#pragma unroll
    for (int k = 0; k < 8; k++) hb[k] = make_float4(0.f, 0.f, 0.f, 0.f);
    double acc[4] = {0.0, 0.0, 0.0, 0.0};             // one chain per component

#pragma unroll 1
    for (int jo = 0; jo < 64; jo += 8) {
#pragma unroll
        for (int e = 0; e < 8; e++) {
            const int j = jo + e;                     // ring slot == e (static)
            if (j >= INROWS) continue;                // uniform predicate
            const int i = r0 - 3 + j;
            const bool ok = ldok && ((unsigned)i < (unsigned)HH);
            const float* rp = colp + (ptrdiff_t)i * WW;

            const float4 z = make_float4(0.f, 0.f, 0.f, 0.f);
            float4 v0 = ok ? __ldg((const float4*)(rp))                    : z;
            float4 v1 = ok ? __ldg((const float4*)(rp + (size_t)1 * HWSZ)) : z;
            float4 v2 = ok ? __ldg((const float4*)(rp + (size_t)2 * HWSZ)) : z;
            float4 v3 = ok ? __ldg((const float4*)(rp + (size_t)3 * HWSZ)) : z;
            float4 v4 = ok ? __ldg((const float4*)(rp + (size_t)4 * HWSZ)) : z;
            float4 v5 = ok ? __ldg((const float4*)(rp + (size_t)5 * HWSZ)) : z;

            const float4 s0 = f4add(f4add(v0, v1), v2);   // frame l channel sum
            const float4 s1 = f4add(f4add(v3, v4), v5);   // frame l+1 channel sum
            const float4 d  = f4sub(s0, s1);

            // neighbor halo: left lane's y,z,w ; right lane's x,y,z
            const float Ly = __shfl_up_sync(0xffffffffu, d.y, 1);
            const float Lz = __shfl_up_sync(0xffffffffu, d.z, 1);
            const float Lw = __shfl_up_sync(0xffffffffu, d.w, 1);
            const float Rx = __shfl_down_sync(0xffffffffu, d.x, 1);
            const float Ry = __shfl_down_sync(0xffffffffu, d.y, 1);
            const float Rz = __shfl_down_sync(0xffffffffu, d.z, 1);

            // horizontal 7-tap box for the 4 owned columns
            float4 h;
            h.x = ((Ly + Lz) + (Lw + d.x)) + ((d.y + d.z) + d.w);
            h.y = ((Lz + Lw) + (d.x + d.y)) + ((d.z + d.w) + Rx);
            h.z = ((Lw + d.x) + (d.y + d.z)) + ((d.w + Rx) + Ry);
            h.w = ((d.x + d.y) + (d.z + d.w)) + ((Rx + Ry) + Rz);
            hb[e] = h;

            if (j >= 6) {                             // output row r0 + j - 6
                const float4 vs =
                    f4add(f4add(f4add(hb[(e)     & 7], hb[(e + 7) & 7]),
                                f4add(hb[(e + 6) & 7], hb[(e + 5) & 7])),
                          f4add(f4add(hb[(e + 4) & 7], hb[(e + 3) & 7]),
                                hb[(e + 2) & 7]));
                if (outok) {
                    acc[0] += (double)fabsf(fmaf(w0, vs.x, EPSF));
                    acc[1] += (double)fabsf(fmaf(w0, vs.y, EPSF));
                    acc[2] += (double)fabsf(fmaf(w0, vs.z, EPSF));
                    acc[3] += (double)fabsf(fmaf(w0, vs.w, EPSF));
                }
            }
        }
    }

    // ---- warp reduction (double), then cross-half combine ----
    double s = (acc[0] + acc[1]) + (acc[2] + acc[3]);
#pragma unroll
    for (int off = 16; off > 0; off >>= 1)
        s += __shfl_down_sync(0xffffffffu, s, off);

    __shared__ double sd[4];
    if (lane == 0) sd[warp] = s;
    __syncthreads();
    if (t < PPB) {
        const int pp = blockIdx.y * PPB + t;
        g_ds4[pp * NCHUNK + chunk] = sd[2 * t] + sd[2 * t + 1];
    }
}

// ---------------- kernel 2: sqrt / normalize / cumsum / argmin (parallel) ----
__global__ __launch_bounds__(512) void select_kernel()
{
    __shared__ double dsp[PAIRS];
    __shared__ double cum[PAIRS];
    const int t = threadIdx.x;

    if (t < PAIRS) {
        const double* q = &g_ds4[t * NCHUNK];
        dsp[t] = sqrt((q[0] + q[1]) + (q[2] + q[3]));
    }
    __syncthreads();

    if (t < BATCH) {
        const double* dp = &dsp[t * (LFRM - 1)];
        double s = 0.0;
        for (int l = 0; l < LFRM - 1; l++) s += dp[l];
        const double inv = 1.0 / s;
        double c = 0.0;
        for (int l = 0; l < LFRM - 1; l++) {
            c += dp[l] * inv;
            cum[t * (LFRM - 1) + l] = c;
        }
    }
    __syncthreads();

    if (t < BATCH * MSEL) {
        const int b = t >> 4, m = t & 15;
        const double* cp = &cum[b * (LFRM - 1)];
        const float interval = 1.0f / (float)(MSEL - 1);
        const double target = (double)((float)m * interval);
        double best = 1e300;
        int bi = 0;
        for (int l = 0; l < LFRM - 1; l++) {
            double d = fabs(cp[l] - target);
            if (d < best) { best = d; bi = l; }   // strict '<' => first occurrence
        }
        g_idx[t] = bi;
    }
}

// ---------------- kernel 3: gather selected frames ---------------------------
__global__ __launch_bounds__(256) void gather_kernel(const float* __restrict__ x,
                                                     float* __restrict__ out)
{
    const int bm = blockIdx.y;             // 0..127
    const int b  = bm >> 4;
    const int src = b * LFRM + g_idx[bm];
    const float4* sp = (const float4*)(x + (size_t)src * (CH * HWSZ));
    float4* dp = (float4*)(out + (size_t)bm * (CH * HWSZ));
    const int i = blockIdx.x * 256 + threadIdx.x;   // 147*256 = 37632 exact
    dp[i] = sp[i];
}

// ---------------- launcher ---------------------------------------------------
extern "C" void kernel_launch(void* const* d_in, const int* in_sizes, int n_in,
                              void* d_out, int out_size)
{
    const float* x = nullptr;
    const float* w = nullptr;
    for (int i = 0; i < n_in; i++) {
        if (in_sizes[i] == FRAMES * CH * HWSZ) x = (const float*)d_in[i];
        else if (in_sizes[i] == CH * 49)       w = (const float*)d_in[i];
    }

    pairdiff_kernel<<<dim3(NCHUNK, NGRP), 128>>>(x, w);
    select_kernel<<<1, 512>>>();
    gather_kernel<<<dim3(147, BATCH * MSEL), 256>>>(x, (float*)d_out);
}